// round 9
// baseline (speedup 1.0000x reference)
#include <cuda_runtime.h>
#include <cstdint>

// LaneAttention, sm_103 (PTX compute_103): tensor-core GEMMs via mma.sync
// m16n8k8 tf32 with split-precision (3-pass), + fp32 attention kernel.
//   KVk: [131072 x 64] @ Wk^T -> g_K [unit][g][l]
//   KVv: [131072 x 64] @ Wv^T -> g_V [unit][g][l]
//   Q:   [61440 x 128] @ Wq^T -> g_Q [m][g]
//   attn (per unit, fp32)     -> g_O [m][g]
//   Y:   [61440 x 128] @ Wc^T + veh -> out

#define TT    30
#define FF    128
#define LL    64
#define LFN   64
#define THN   20
#define NUNIT 2048
#define NROWQ (TT*NUNIT)   // 61440

typedef unsigned long long u64;

// ---------------- scratch (static device arrays) ----------------
__device__ float g_K[NUNIT * 128 * 64];
__device__ float g_V[NUNIT * 128 * 64];
__device__ float g_Q[NROWQ * 128];
__device__ float g_O[NROWQ * 128];

// ---------------- tf32 helpers ----------------
__device__ __forceinline__ uint32_t to_tf32(float x) {
    uint32_t r;
    asm("cvt.rna.tf32.f32 %0, %1;" : "=r"(r) : "f"(x));
    return r;
}
__device__ __forceinline__ void mma_tf32(float* d, const uint32_t* a,
                                         uint32_t b0, uint32_t b1) {
    asm volatile(
        "mma.sync.aligned.m16n8k8.row.col.f32.tf32.tf32.f32 "
        "{%0,%1,%2,%3}, {%4,%5,%6,%7}, {%8,%9}, {%0,%1,%2,%3};"
        : "+f"(d[0]), "+f"(d[1]), "+f"(d[2]), "+f"(d[3])
        : "r"(a[0]), "r"(a[1]), "r"(a[2]), "r"(a[3]), "r"(b0), "r"(b1));
}
__device__ __forceinline__ uint32_t f2u(float x) { return __float_as_uint(x); }

// Stage [rows x 64] fp32 tile (row stride ld) into hi/lo tf32 SMEM tiles, ld 68.
__device__ __forceinline__ void stage_split(float* hi, float* lo,
                                            const float* __restrict__ src,
                                            int ld, int rows, int tid, int nthr)
{
    const int total4 = rows * 16;   // rows * 64 / 4
    for (int i4 = tid; i4 < total4; i4 += nthr) {
        int r = i4 >> 4, k = (i4 & 15) * 4;
        float4 v = *(const float4*)&src[(size_t)r * ld + k];
        uint32_t hx = to_tf32(v.x), hy = to_tf32(v.y),
                 hz = to_tf32(v.z), hw = to_tf32(v.w);
        float lx = v.x - __uint_as_float(hx);
        float ly = v.y - __uint_as_float(hy);
        float lz = v.z - __uint_as_float(hz);
        float lw = v.w - __uint_as_float(hw);
        int o = r * 68 + k;
        *(uint4*)&hi[o] = make_uint4(hx, hy, hz, hw);
        *(uint4*)&lo[o] = make_uint4(to_tf32(lx), to_tf32(ly),
                                     to_tf32(lz), to_tf32(lw));
    }
}

// SMEM float offsets for GEMM kernels (tiles [128][68])
#define AH_OFF 0
#define AL_OFF 8704
#define BH_OFF 17408
#define BL_OFF 26112
#define GEMM_SMEM_FLOATS 34816     // 139264 B
#define GEMM_SMEM (GEMM_SMEM_FLOATS * 4)

// Run one K=64 block-tile of mma: warp (wm, wn), accum d[2][8][4].
__device__ __forceinline__ void mma_k64(const float* sm, float d[2][8][4],
                                        int wm, int wn, int qr, int qc)
{
    #pragma unroll 1
    for (int ks = 0; ks < 8; ks++) {
        const int kb = ks * 8 + qc;
        uint32_t ah[2][4], al[2][4];
        #pragma unroll
        for (int i = 0; i < 2; i++) {
            int r0 = (wm + i * 16 + qr) * 68;
            ah[i][0] = f2u(sm[AH_OFF + r0 + kb]);
            ah[i][1] = f2u(sm[AH_OFF + r0 + 8 * 68 + kb]);
            ah[i][2] = f2u(sm[AH_OFF + r0 + kb + 4]);
            ah[i][3] = f2u(sm[AH_OFF + r0 + 8 * 68 + kb + 4]);
            al[i][0] = f2u(sm[AL_OFF + r0 + kb]);
            al[i][1] = f2u(sm[AL_OFF + r0 + 8 * 68 + kb]);
            al[i][2] = f2u(sm[AL_OFF + r0 + kb + 4]);
            al[i][3] = f2u(sm[AL_OFF + r0 + 8 * 68 + kb + 4]);
        }
        #pragma unroll
        for (int j = 0; j < 8; j++) {
            int nb = (wn + j * 8 + qr) * 68;
            uint32_t bh0 = f2u(sm[BH_OFF + nb + kb]);
            uint32_t bh1 = f2u(sm[BH_OFF + nb + kb + 4]);
            uint32_t bl0 = f2u(sm[BL_OFF + nb + kb]);
            uint32_t bl1 = f2u(sm[BL_OFF + nb + kb + 4]);
            #pragma unroll
            for (int i = 0; i < 2; i++) {
                mma_tf32(d[i][j], ah[i], bh0, bh1);
                mma_tf32(d[i][j], ah[i], bl0, bl1);
                mma_tf32(d[i][j], al[i], bh0, bh1);
            }
        }
    }
}

// ================= KV GEMM =================
// grid.x = 2048: mt = bid>>1 (128-row tile of lanes), nt = bid&1 (0: Wk->g_K, 1: Wv->g_V)
__global__ void __launch_bounds__(256, 1)
kv_gemm(const float* __restrict__ lanes, const float* __restrict__ Wk,
        const float* __restrict__ Wv)
{
    extern __shared__ float sm[];
    const int tid = threadIdx.x, wid = tid >> 5, lane = tid & 31;
    const int qr = lane >> 2, qc = lane & 3;
    const int mt = blockIdx.x >> 1, nt = blockIdx.x & 1;
    const int wm = (wid >> 1) * 32, wn = (wid & 1) * 64;

    stage_split(sm + AH_OFF, sm + AL_OFF, lanes + (size_t)mt * 128 * 64, 64, 128, tid, 256);
    stage_split(sm + BH_OFF, sm + BL_OFF, nt ? Wv : Wk, 64, 128, tid, 256);
    __syncthreads();

    float d[2][8][4];
    #pragma unroll
    for (int i = 0; i < 2; i++)
        #pragma unroll
        for (int j = 0; j < 8; j++)
            d[i][j][0] = d[i][j][1] = d[i][j][2] = d[i][j][3] = 0.f;

    mma_k64(sm, d, wm, wn, qr, qc);
    __syncthreads();   // tiles dead; reuse as transpose buffer T[128][129]

    #pragma unroll
    for (int i = 0; i < 2; i++)
        #pragma unroll
        for (int j = 0; j < 8; j++) {
            int r = wm + i * 16 + qr, c = wn + j * 8 + 2 * qc;
            sm[r * 129 + c]           = d[i][j][0];
            sm[r * 129 + c + 1]       = d[i][j][1];
            sm[(r + 8) * 129 + c]     = d[i][j][2];
            sm[(r + 8) * 129 + c + 1] = d[i][j][3];
        }
    __syncthreads();

    float* dst = nt ? g_V : g_K;
    // block covers units u0, u0+1 (rows m = u_local*64 + l), cols g 0..127
    const int u0 = mt * 2;
    for (int idx = tid; idx < 128 * 128; idx += 256) {
        int u = idx >> 13, rem = idx & 8191;
        int g = rem >> 6, l = rem & 63;
        dst[(size_t)(u0 + u) * 8192 + g * 64 + l] = sm[(u * 64 + l) * 129 + g];
    }
}

// ================= Q / Y GEMM (K=128 in two halves) =================
__global__ void __launch_bounds__(256, 1)
q_gemm(const float* __restrict__ veh, const float* __restrict__ Wq)
{
    extern __shared__ float sm[];
    const int tid = threadIdx.x, wid = tid >> 5, lane = tid & 31;
    const int qr = lane >> 2, qc = lane & 3;
    const int m0 = blockIdx.x * 128;
    const int wm = (wid >> 1) * 32, wn = (wid & 1) * 64;

    float d[2][8][4];
    #pragma unroll
    for (int i = 0; i < 2; i++)
        #pragma unroll
        for (int j = 0; j < 8; j++)
            d[i][j][0] = d[i][j][1] = d[i][j][2] = d[i][j][3] = 0.f;

    #pragma unroll 1
    for (int kh = 0; kh < 2; kh++) {
        stage_split(sm + AH_OFF, sm + AL_OFF, veh + (size_t)m0 * 128 + kh * 64, 128, 128, tid, 256);
        stage_split(sm + BH_OFF, sm + BL_OFF, Wq + kh * 64, 128, 128, tid, 256);
        __syncthreads();
        mma_k64(sm, d, wm, wn, qr, qc);
        __syncthreads();
    }

    #pragma unroll
    for (int i = 0; i < 2; i++)
        #pragma unroll
        for (int j = 0; j < 8; j++) {
            int r = m0 + wm + i * 16 + qr, c = wn + j * 8 + 2 * qc;
            *(float2*)&g_Q[(size_t)r * 128 + c]       = make_float2(d[i][j][0], d[i][j][1]);
            *(float2*)&g_Q[(size_t)(r + 8) * 128 + c] = make_float2(d[i][j][2], d[i][j][3]);
        }
}

__global__ void __launch_bounds__(256, 1)
y_gemm(const float* __restrict__ Wc, const float* __restrict__ veh,
       float* __restrict__ out)
{
    extern __shared__ float sm[];
    const int tid = threadIdx.x, wid = tid >> 5, lane = tid & 31;
    const int qr = lane >> 2, qc = lane & 3;
    const int m0 = blockIdx.x * 128;
    const int wm = (wid >> 1) * 32, wn = (wid & 1) * 64;

    float d[2][8][4];
    #pragma unroll
    for (int i = 0; i < 2; i++)
        #pragma unroll
        for (int j = 0; j < 8; j++)
            d[i][j][0] = d[i][j][1] = d[i][j][2] = d[i][j][3] = 0.f;

    #pragma unroll 1
    for (int kh = 0; kh < 2; kh++) {
        stage_split(sm + AH_OFF, sm + AL_OFF, g_O + (size_t)m0 * 128 + kh * 64, 128, 128, tid, 256);
        stage_split(sm + BH_OFF, sm + BL_OFF, Wc + kh * 64, 128, 128, tid, 256);
        __syncthreads();
        mma_k64(sm, d, wm, wn, qr, qc);
        __syncthreads();
    }

    #pragma unroll
    for (int i = 0; i < 2; i++)
        #pragma unroll
        for (int j = 0; j < 8; j++) {
            int r = m0 + wm + i * 16 + qr, c = wn + j * 8 + 2 * qc;
            size_t o0 = (size_t)r * 128 + c, o1 = (size_t)(r + 8) * 128 + c;
            float2 x0 = *(const float2*)&veh[o0];
            float2 x1 = *(const float2*)&veh[o1];
            *(float2*)&out[o0] = make_float2(d[i][j][0] + x0.x, d[i][j][1] + x0.y);
            *(float2*)&out[o1] = make_float2(d[i][j][2] + x1.x, d[i][j][3] + x1.y);
        }
}

// ================= attention kernel (fp32, per-unit) =================
#define AKT_OFF 0
#define AVT_OFF 8320
#define AQ_OFF  16640
#define AP_OFF  20600
#define A_SMEM_FLOATS 28280   // 113120 B -> 2 CTAs/SM

__device__ __forceinline__ u64 ffma2(u64 a, u64 b, u64 c) {
    u64 d;
    asm("fma.rn.f32x2 %0, %1, %2, %3;" : "=l"(d) : "l"(a), "l"(b), "l"(c));
    return d;
}
__device__ __forceinline__ u64 dup2(float x) {
    u64 d; asm("mov.b64 %0, {%1, %1};" : "=l"(d) : "f"(x)); return d;
}
__device__ __forceinline__ u64 pack2(float lo, float hi) {
    u64 d; asm("mov.b64 %0, {%1, %2};" : "=l"(d) : "f"(lo), "f"(hi)); return d;
}
__device__ __forceinline__ float2 unpack2(u64 a) {
    float2 r; asm("mov.b64 {%0, %1}, %2;" : "=f"(r.x), "=f"(r.y) : "l"(a)); return r;
}

__global__ void __launch_bounds__(512, 2)
attn_kernel(const int* __restrict__ maskl)
{
    extern __shared__ float sm[];
    const int tid  = threadIdx.x;
    const int w    = tid >> 5;
    const int lane = tid & 31;
    const int bid  = blockIdx.x;
    const int ah   = w & 3;
    const int atw  = w >> 2;

    int mi0 = 0, mi1 = 0;
    #pragma unroll
    for (int th = 0; th < THN; th++) {
        const int* mp = maskl + (size_t)(th * NUNIT + bid) * LL;
        mi0 |= mp[lane];
        mi1 |= mp[lane + 32];
    }
    const bool km0 = (mi0 != 0), km1 = (mi1 != 0);

    {
        const float* kp = g_K + (size_t)bid * 8192;
        const float* vp = g_V + (size_t)bid * 8192;
        for (int idx = tid; idx < 8192; idx += 512) {
            int g = idx >> 6, l = idx & 63;
            sm[AKT_OFF + g * 65 + l] = kp[idx];
            sm[AVT_OFF + g * 65 + l] = vp[idx];
        }
        for (int idx = tid; idx < TT * FF; idx += 512) {
            int t = idx >> 7, g = idx & 127;
            sm[AQ_OFF + t * 132 + g] = g_Q[(size_t)(t * NUNIT + bid) * 128 + g];
        }
    }
    __syncthreads();

    {
        const int gb = ah * 32;
        u64 acc[8] = {0,0,0,0,0,0,0,0};
        #pragma unroll 2
        for (int d = 0; d < 32; d += 4) {
            u64 kk[4];
            #pragma unroll
            for (int j = 0; j < 4; j++) {
                float k0 = sm[AKT_OFF + (gb + d + j) * 65 + lane];
                float k1 = sm[AKT_OFF + (gb + d + j) * 65 + lane + 32];
                kk[j] = pack2(k0, k1);
            }
            #pragma unroll
            for (int it = 0; it < 8; it++) {
                int tr = atw * 8 + it; tr = tr < TT ? tr : (TT - 1);
                float4 q = *(const float4*)&sm[AQ_OFF + tr * 132 + gb + d];
                acc[it] = ffma2(dup2(q.x), kk[0], acc[it]);
                acc[it] = ffma2(dup2(q.y), kk[1], acc[it]);
                acc[it] = ffma2(dup2(q.z), kk[2], acc[it]);
                acc[it] = ffma2(dup2(q.w), kk[3], acc[it]);
            }
        }
        const float scale = 0.17677669529663687f;
        #pragma unroll
        for (int it = 0; it < 8; it++) {
            int t = atw * 8 + it;
            if (t >= TT) break;
            float2 sc = unpack2(acc[it]);
            float s0 = km0 ? sc.x * scale : -1e9f;
            float s1 = km1 ? sc.y * scale : -1e9f;
            float m = fmaxf(s0, s1);
            #pragma unroll
            for (int o = 16; o; o >>= 1) m = fmaxf(m, __shfl_xor_sync(0xffffffffu, m, o));
            float e0 = __expf(s0 - m), e1 = __expf(s1 - m);
            float ss = e0 + e1;
            #pragma unroll
            for (int o = 16; o; o >>= 1) ss += __shfl_xor_sync(0xffffffffu, ss, o);
            float inv = 1.0f / ss;
            sm[AP_OFF + t * 256 + ah * 64 + lane]      = e0 * inv;
            sm[AP_OFF + t * 256 + ah * 64 + lane + 32] = e1 * inv;
        }
    }
    __syncthreads();

    {
        const int gb = ah * 32;
        const int vrow = AVT_OFF + (gb + lane) * 65;
        float oacc[8] = {0,0,0,0,0,0,0,0};
        #pragma unroll 2
        for (int l = 0; l < LL; l += 4) {
            float v0 = sm[vrow + l + 0];
            float v1 = sm[vrow + l + 1];
            float v2 = sm[vrow + l + 2];
            float v3 = sm[vrow + l + 3];
            #pragma unroll
            for (int it = 0; it < 8; it++) {
                int tr = atw * 8 + it; tr = tr < TT ? tr : (TT - 1);
                float4 p = *(const float4*)&sm[AP_OFF + tr * 256 + ah * 64 + l];
                oacc[it] = fmaf(p.x, v0, fmaf(p.y, v1, fmaf(p.z, v2, fmaf(p.w, v3, oacc[it]))));
            }
        }
        #pragma unroll
        for (int it = 0; it < 8; it++) {
            int t = atw * 8 + it;
            if (t < TT)
                g_O[(size_t)(t * NUNIT + bid) * 128 + gb + lane] = oacc[it];
        }
    }
}

// ================= launcher =================
extern "C" void kernel_launch(void* const* d_in, const int* in_sizes, int n_in,
                              void* d_out, int out_size)
{
    const float* veh   = (const float*)d_in[0];
    const float* lanes = (const float*)d_in[1];
    const int*   maskl = (const int*)d_in[2];
    const float* Wk    = (const float*)d_in[3];
    const float* Wv    = (const float*)d_in[4];
    const float* Wq    = (const float*)d_in[5];
    const float* Wc    = (const float*)d_in[6];
    float* out = (float*)d_out;

    cudaFuncSetAttribute(kv_gemm, cudaFuncAttributeMaxDynamicSharedMemorySize, GEMM_SMEM);
    cudaFuncSetAttribute(q_gemm,  cudaFuncAttributeMaxDynamicSharedMemorySize, GEMM_SMEM);
    cudaFuncSetAttribute(y_gemm,  cudaFuncAttributeMaxDynamicSharedMemorySize, GEMM_SMEM);
    cudaFuncSetAttribute(attn_kernel, cudaFuncAttributeMaxDynamicSharedMemorySize,
                         A_SMEM_FLOATS * (int)sizeof(float));

    kv_gemm<<<NUNIT, 256, GEMM_SMEM>>>(lanes, Wk, Wv);          // 2048 blocks
    q_gemm<<<NROWQ / 128, 256, GEMM_SMEM>>>(veh, Wq);           // 480 blocks
    attn_kernel<<<NUNIT, 512, A_SMEM_FLOATS * sizeof(float)>>>(maskl);
    y_gemm<<<NROWQ / 128, 256, GEMM_SMEM>>>(Wc, veh, out);      // 480 blocks
}

// round 10
// speedup vs baseline: 1.1834x; 1.1834x over previous
#include <cuda_runtime.h>
#include <cstdint>

// LaneAttention, sm_103 (PTX compute_103): mma.sync tf32 split-precision GEMMs
// + fp32 attention kernel.
//   KV (swapped, persistent): Kt[u][g][l] = W x lanes^T  -> g_K, g_V
//   Q:   [61440 x 128] @ Wq^T -> g_Q [m][g]
//   attn (per unit, fp32)     -> g_O [m][g]
//   Y:   [61440 x 128] @ Wc^T + veh -> out

#define TT    30
#define FF    128
#define LL    64
#define LFN   64
#define THN   20
#define NUNIT 2048
#define NROWQ (TT*NUNIT)   // 61440

typedef unsigned long long u64;

// ---------------- scratch ----------------
__device__ float g_K[NUNIT * 128 * 64];
__device__ float g_V[NUNIT * 128 * 64];
__device__ float g_Q[NROWQ * 128];
__device__ float g_O[NROWQ * 128];

// ---------------- tf32 helpers ----------------
__device__ __forceinline__ uint32_t to_tf32(float x) {
    uint32_t r;
    asm("cvt.rna.tf32.f32 %0, %1;" : "=r"(r) : "f"(x));
    return r;
}
__device__ __forceinline__ void mma_tf32(float* d, const uint32_t* a,
                                         uint32_t b0, uint32_t b1) {
    asm volatile(
        "mma.sync.aligned.m16n8k8.row.col.f32.tf32.tf32.f32 "
        "{%0,%1,%2,%3}, {%4,%5,%6,%7}, {%8,%9}, {%0,%1,%2,%3};"
        : "+f"(d[0]), "+f"(d[1]), "+f"(d[2]), "+f"(d[3])
        : "r"(a[0]), "r"(a[1]), "r"(a[2]), "r"(a[3]), "r"(b0), "r"(b1));
}
__device__ __forceinline__ uint32_t f2u(float x) { return __float_as_uint(x); }

// Stage [rows x 64] fp32 tile (row stride ld) into hi/lo tf32 SMEM tiles, ld 68.
__device__ __forceinline__ void stage_split(float* hi, float* lo,
                                            const float* __restrict__ src,
                                            int ld, int rows, int tid, int nthr)
{
    const int total4 = rows * 16;
    for (int i4 = tid; i4 < total4; i4 += nthr) {
        int r = i4 >> 4, k = (i4 & 15) * 4;
        float4 v = *(const float4*)&src[(size_t)r * ld + k];
        uint32_t hx = to_tf32(v.x), hy = to_tf32(v.y),
                 hz = to_tf32(v.z), hw = to_tf32(v.w);
        float lx = v.x - __uint_as_float(hx);
        float ly = v.y - __uint_as_float(hy);
        float lz = v.z - __uint_as_float(hz);
        float lw = v.w - __uint_as_float(hw);
        int o = r * 68 + k;
        *(uint4*)&hi[o] = make_uint4(hx, hy, hz, hw);
        *(uint4*)&lo[o] = make_uint4(to_tf32(lx), to_tf32(ly),
                                     to_tf32(lz), to_tf32(lw));
    }
}

// SMEM float offsets (tiles [128][68])
#define AH_OFF 0
#define AL_OFF 8704
#define BH_OFF 17408
#define BL_OFF 26112
#define GEMM_SMEM_FLOATS 34816     // 139264 B
#define GEMM_SMEM (GEMM_SMEM_FLOATS * 4)

// One K=64 block-tile of split mma: warp tile (wm, wn), accum d[2][8][4].
__device__ __forceinline__ void mma_k64(const float* sm, float d[2][8][4],
                                        int wm, int wn, int qr, int qc)
{
    #pragma unroll 1
    for (int ks = 0; ks < 8; ks++) {
        const int kb = ks * 8 + qc;
        uint32_t ah[2][4], al[2][4];
        #pragma unroll
        for (int i = 0; i < 2; i++) {
            int r0 = (wm + i * 16 + qr) * 68;
            ah[i][0] = f2u(sm[AH_OFF + r0 + kb]);
            ah[i][1] = f2u(sm[AH_OFF + r0 + 8 * 68 + kb]);
            ah[i][2] = f2u(sm[AH_OFF + r0 + kb + 4]);
            ah[i][3] = f2u(sm[AH_OFF + r0 + 8 * 68 + kb + 4]);
            al[i][0] = f2u(sm[AL_OFF + r0 + kb]);
            al[i][1] = f2u(sm[AL_OFF + r0 + 8 * 68 + kb]);
            al[i][2] = f2u(sm[AL_OFF + r0 + kb + 4]);
            al[i][3] = f2u(sm[AL_OFF + r0 + 8 * 68 + kb + 4]);
        }
        #pragma unroll
        for (int j = 0; j < 8; j++) {
            int nb = (wn + j * 8 + qr) * 68;
            uint32_t bh0 = f2u(sm[BH_OFF + nb + kb]);
            uint32_t bh1 = f2u(sm[BH_OFF + nb + kb + 4]);
            uint32_t bl0 = f2u(sm[BL_OFF + nb + kb]);
            uint32_t bl1 = f2u(sm[BL_OFF + nb + kb + 4]);
            #pragma unroll
            for (int i = 0; i < 2; i++) {
                mma_tf32(d[i][j], ah[i], bh0, bh1);
                mma_tf32(d[i][j], ah[i], bl0, bl1);
                mma_tf32(d[i][j], al[i], bh0, bh1);
            }
        }
    }
}

// ================= KV GEMM (swapped, persistent) =================
// grid = 2*148: nt = bid/148 (0:Wk->g_K, 1:Wv->g_V), b2 = bid%148.
// Block stages its weight tile (A = [128 g x 64 f]) ONCE, then loops lanes
// n-tiles (B = [128 rows x 64]). Output D[g][m] stored directly to [u][g][l].
__global__ void __launch_bounds__(256, 1)
kv_gemm(const float* __restrict__ lanes, const float* __restrict__ Wk,
        const float* __restrict__ Wv)
{
    extern __shared__ float sm[];
    const int tid = threadIdx.x, wid = tid >> 5, lane = tid & 31;
    const int qr = lane >> 2, qc = lane & 3;
    const int nt = blockIdx.x / 148, b2 = blockIdx.x % 148;
    const int wm = (wid >> 1) * 32, wn = (wid & 1) * 64;

    stage_split(sm + AH_OFF, sm + AL_OFF, nt ? Wv : Wk, 64, 128, tid, 256);
    float* dst = nt ? g_V : g_K;

    #pragma unroll 1
    for (int ntile = b2; ntile < 1024; ntile += 148) {
        __syncthreads();   // prior mma done before overwriting B
        stage_split(sm + BH_OFF, sm + BL_OFF, lanes + (size_t)ntile * 128 * 64,
                    64, 128, tid, 256);
        __syncthreads();

        float d[2][8][4];
        #pragma unroll
        for (int i = 0; i < 2; i++)
            #pragma unroll
            for (int j = 0; j < 8; j++)
                d[i][j][0] = d[i][j][1] = d[i][j][2] = d[i][j][3] = 0.f;

        mma_k64(sm, d, wm, wn, qr, qc);

        const int u0 = ntile * 2;   // 128 rows = 2 units
        #pragma unroll
        for (int i = 0; i < 2; i++)
            #pragma unroll
            for (int j = 0; j < 8; j++) {
                int g = wm + i * 16 + qr;
                int c = wn + j * 8 + 2 * qc;
                int u = u0 + (c >> 6), l = c & 63;
                *(float2*)&dst[(size_t)u * 8192 + g * 64 + l] =
                    make_float2(d[i][j][0], d[i][j][1]);
                *(float2*)&dst[(size_t)u * 8192 + (g + 8) * 64 + l] =
                    make_float2(d[i][j][2], d[i][j][3]);
            }
    }
}

// ================= Q / Y GEMM (K=128 in two halves) =================
__global__ void __launch_bounds__(256, 1)
q_gemm(const float* __restrict__ veh, const float* __restrict__ Wq)
{
    extern __shared__ float sm[];
    const int tid = threadIdx.x, wid = tid >> 5, lane = tid & 31;
    const int qr = lane >> 2, qc = lane & 3;
    const int m0 = blockIdx.x * 128;
    const int wm = (wid >> 1) * 32, wn = (wid & 1) * 64;

    float d[2][8][4];
    #pragma unroll
    for (int i = 0; i < 2; i++)
        #pragma unroll
        for (int j = 0; j < 8; j++)
            d[i][j][0] = d[i][j][1] = d[i][j][2] = d[i][j][3] = 0.f;

    #pragma unroll 1
    for (int kh = 0; kh < 2; kh++) {
        stage_split(sm + AH_OFF, sm + AL_OFF, veh + (size_t)m0 * 128 + kh * 64, 128, 128, tid, 256);
        stage_split(sm + BH_OFF, sm + BL_OFF, Wq + kh * 64, 128, 128, tid, 256);
        __syncthreads();
        mma_k64(sm, d, wm, wn, qr, qc);
        __syncthreads();
    }

    #pragma unroll
    for (int i = 0; i < 2; i++)
        #pragma unroll
        for (int j = 0; j < 8; j++) {
            int r = m0 + wm + i * 16 + qr, c = wn + j * 8 + 2 * qc;
            *(float2*)&g_Q[(size_t)r * 128 + c]       = make_float2(d[i][j][0], d[i][j][1]);
            *(float2*)&g_Q[(size_t)(r + 8) * 128 + c] = make_float2(d[i][j][2], d[i][j][3]);
        }
}

__global__ void __launch_bounds__(256, 1)
y_gemm(const float* __restrict__ Wc, const float* __restrict__ veh,
       float* __restrict__ out)
{
    extern __shared__ float sm[];
    const int tid = threadIdx.x, wid = tid >> 5, lane = tid & 31;
    const int qr = lane >> 2, qc = lane & 3;
    const int m0 = blockIdx.x * 128;
    const int wm = (wid >> 1) * 32, wn = (wid & 1) * 64;

    float d[2][8][4];
    #pragma unroll
    for (int i = 0; i < 2; i++)
        #pragma unroll
        for (int j = 0; j < 8; j++)
            d[i][j][0] = d[i][j][1] = d[i][j][2] = d[i][j][3] = 0.f;

    #pragma unroll 1
    for (int kh = 0; kh < 2; kh++) {
        stage_split(sm + AH_OFF, sm + AL_OFF, g_O + (size_t)m0 * 128 + kh * 64, 128, 128, tid, 256);
        stage_split(sm + BH_OFF, sm + BL_OFF, Wc + kh * 64, 128, 128, tid, 256);
        __syncthreads();
        mma_k64(sm, d, wm, wn, qr, qc);
        __syncthreads();
    }

    #pragma unroll
    for (int i = 0; i < 2; i++)
        #pragma unroll
        for (int j = 0; j < 8; j++) {
            int r = m0 + wm + i * 16 + qr, c = wn + j * 8 + 2 * qc;
            size_t o0 = (size_t)r * 128 + c, o1 = (size_t)(r + 8) * 128 + c;
            float2 x0 = *(const float2*)&veh[o0];
            float2 x1 = *(const float2*)&veh[o1];
            *(float2*)&out[o0] = make_float2(d[i][j][0] + x0.x, d[i][j][1] + x0.y);
            *(float2*)&out[o1] = make_float2(d[i][j][2] + x1.x, d[i][j][3] + x1.y);
        }
}

// ================= attention kernel (fp32, per-unit) =================
#define AKT_OFF 0
#define AVT_OFF 8320
#define AQ_OFF  16640
#define AP_OFF  20600
#define A_SMEM_FLOATS 28280   // 113120 B -> 2 CTAs/SM

__device__ __forceinline__ u64 ffma2(u64 a, u64 b, u64 c) {
    u64 d;
    asm("fma.rn.f32x2 %0, %1, %2, %3;" : "=l"(d) : "l"(a), "l"(b), "l"(c));
    return d;
}
__device__ __forceinline__ u64 dup2(float x) {
    u64 d; asm("mov.b64 %0, {%1, %1};" : "=l"(d) : "f"(x)); return d;
}
__device__ __forceinline__ u64 pack2(float lo, float hi) {
    u64 d; asm("mov.b64 %0, {%1, %2};" : "=l"(d) : "f"(lo), "f"(hi)); return d;
}
__device__ __forceinline__ float2 unpack2(u64 a) {
    float2 r; asm("mov.b64 {%0, %1}, %2;" : "=f"(r.x), "=f"(r.y) : "l"(a)); return r;
}

__global__ void __launch_bounds__(512, 2)
attn_kernel(const int* __restrict__ maskl)
{
    extern __shared__ float sm[];
    const int tid  = threadIdx.x;
    const int w    = tid >> 5;
    const int lane = tid & 31;
    const int bid  = blockIdx.x;
    const int ah   = w & 3;
    const int atw  = w >> 2;

    int mi0 = 0, mi1 = 0;
    #pragma unroll
    for (int th = 0; th < THN; th++) {
        const int* mp = maskl + (size_t)(th * NUNIT + bid) * LL;
        mi0 |= mp[lane];
        mi1 |= mp[lane + 32];
    }
    const bool km0 = (mi0 != 0), km1 = (mi1 != 0);

    {
        const float* kp = g_K + (size_t)bid * 8192;
        const float* vp = g_V + (size_t)bid * 8192;
        for (int idx = tid; idx < 8192; idx += 512) {
            int g = idx >> 6, l = idx & 63;
            sm[AKT_OFF + g * 65 + l] = kp[idx];
            sm[AVT_OFF + g * 65 + l] = vp[idx];
        }
        for (int idx = tid; idx < TT * FF; idx += 512) {
            int t = idx >> 7, g = idx & 127;
            sm[AQ_OFF + t * 132 + g] = g_Q[(size_t)(t * NUNIT + bid) * 128 + g];
        }
    }
    __syncthreads();

    {
        const int gb = ah * 32;
        u64 acc[8] = {0,0,0,0,0,0,0,0};
        #pragma unroll 2
        for (int d = 0; d < 32; d += 4) {
            u64 kk[4];
            #pragma unroll
            for (int j = 0; j < 4; j++) {
                float k0 = sm[AKT_OFF + (gb + d + j) * 65 + lane];
                float k1 = sm[AKT_OFF + (gb + d + j) * 65 + lane + 32];
                kk[j] = pack2(k0, k1);
            }
            #pragma unroll
            for (int it = 0; it < 8; it++) {
                int tr = atw * 8 + it; tr = tr < TT ? tr : (TT - 1);
                float4 q = *(const float4*)&sm[AQ_OFF + tr * 132 + gb + d];
                acc[it] = ffma2(dup2(q.x), kk[0], acc[it]);
                acc[it] = ffma2(dup2(q.y), kk[1], acc[it]);
                acc[it] = ffma2(dup2(q.z), kk[2], acc[it]);
                acc[it] = ffma2(dup2(q.w), kk[3], acc[it]);
            }
        }
        const float scale = 0.17677669529663687f;
        #pragma unroll
        for (int it = 0; it < 8; it++) {
            int t = atw * 8 + it;
            if (t >= TT) break;
            float2 sc = unpack2(acc[it]);
            float s0 = km0 ? sc.x * scale : -1e9f;
            float s1 = km1 ? sc.y * scale : -1e9f;
            float m = fmaxf(s0, s1);
            #pragma unroll
            for (int o = 16; o; o >>= 1) m = fmaxf(m, __shfl_xor_sync(0xffffffffu, m, o));
            float e0 = __expf(s0 - m), e1 = __expf(s1 - m);
            float ss = e0 + e1;
            #pragma unroll
            for (int o = 16; o; o >>= 1) ss += __shfl_xor_sync(0xffffffffu, ss, o);
            float inv = 1.0f / ss;
            sm[AP_OFF + t * 256 + ah * 64 + lane]      = e0 * inv;
            sm[AP_OFF + t * 256 + ah * 64 + lane + 32] = e1 * inv;
        }
    }
    __syncthreads();

    {
        const int gb = ah * 32;
        const int vrow = AVT_OFF + (gb + lane) * 65;
        float oacc[8] = {0,0,0,0,0,0,0,0};
        #pragma unroll 2
        for (int l = 0; l < LL; l += 4) {
            float v0 = sm[vrow + l + 0];
            float v1 = sm[vrow + l + 1];
            float v2 = sm[vrow + l + 2];
            float v3 = sm[vrow + l + 3];
            #pragma unroll
            for (int it = 0; it < 8; it++) {
                int tr = atw * 8 + it; tr = tr < TT ? tr : (TT - 1);
                float4 p = *(const float4*)&sm[AP_OFF + tr * 256 + ah * 64 + l];
                oacc[it] = fmaf(p.x, v0, fmaf(p.y, v1, fmaf(p.z, v2, fmaf(p.w, v3, oacc[it]))));
            }
        }
        #pragma unroll
        for (int it = 0; it < 8; it++) {
            int t = atw * 8 + it;
            if (t < TT)
                g_O[(size_t)(t * NUNIT + bid) * 128 + gb + lane] = oacc[it];
        }
    }
}

// ================= launcher =================
extern "C" void kernel_launch(void* const* d_in, const int* in_sizes, int n_in,
                              void* d_out, int out_size)
{
    const float* veh   = (const float*)d_in[0];
    const float* lanes = (const float*)d_in[1];
    const int*   maskl = (const int*)d_in[2];
    const float* Wk    = (const float*)d_in[3];
    const float* Wv    = (const float*)d_in[4];
    const float* Wq    = (const float*)d_in[5];
    const float* Wc    = (const float*)d_in[6];
    float* out = (float*)d_out;

    cudaFuncSetAttribute(kv_gemm, cudaFuncAttributeMaxDynamicSharedMemorySize, GEMM_SMEM);
    cudaFuncSetAttribute(q_gemm,  cudaFuncAttributeMaxDynamicSharedMemorySize, GEMM_SMEM);
    cudaFuncSetAttribute(y_gemm,  cudaFuncAttributeMaxDynamicSharedMemorySize, GEMM_SMEM);
    cudaFuncSetAttribute(attn_kernel, cudaFuncAttributeMaxDynamicSharedMemorySize,
                         A_SMEM_FLOATS * (int)sizeof(float));

    kv_gemm<<<2 * 148, 256, GEMM_SMEM>>>(lanes, Wk, Wv);
    q_gemm<<<NROWQ / 128, 256, GEMM_SMEM>>>(veh, Wq);
    attn_kernel<<<NUNIT, 512, A_SMEM_FLOATS * sizeof(float)>>>(maskl);
    y_gemm<<<NROWQ / 128, 256, GEMM_SMEM>>>(Wc, veh, out);
}

// round 11
// speedup vs baseline: 1.1908x; 1.0063x over previous
#include <cuda_runtime.h>
#include <cstdint>

// LaneAttention, sm_103: mma.sync tf32 split-precision GEMMs (K=32 chunks,
// 2 CTAs/SM) + fp32 attention kernel.
//   KV (swapped, persistent): Kt[u][g][l] = W x lanes^T  -> g_K, g_V
//   Q:   [61440 x 128] @ Wq^T -> g_Q [m][g]
//   attn (per unit, fp32)     -> g_O [m][g]
//   Y:   [61440 x 128] @ Wc^T + veh -> out

#define TT    30
#define FF    128
#define LL    64
#define LFN   64
#define THN   20
#define NUNIT 2048
#define NROWQ (TT*NUNIT)   // 61440

typedef unsigned long long u64;

// ---------------- scratch ----------------
__device__ float g_K[NUNIT * 128 * 64];
__device__ float g_V[NUNIT * 128 * 64];
__device__ float g_Q[NROWQ * 128];
__device__ float g_O[NROWQ * 128];

// ---------------- tf32 helpers ----------------
__device__ __forceinline__ uint32_t to_tf32(float x) {
    uint32_t r;
    asm("cvt.rna.tf32.f32 %0, %1;" : "=r"(r) : "f"(x));
    return r;
}
__device__ __forceinline__ void mma_tf32(float* d, const uint32_t* a,
                                         uint32_t b0, uint32_t b1) {
    asm volatile(
        "mma.sync.aligned.m16n8k8.row.col.f32.tf32.tf32.f32 "
        "{%0,%1,%2,%3}, {%4,%5,%6,%7}, {%8,%9}, {%0,%1,%2,%3};"
        : "+f"(d[0]), "+f"(d[1]), "+f"(d[2]), "+f"(d[3])
        : "r"(a[0]), "r"(a[1]), "r"(a[2]), "r"(a[3]), "r"(b0), "r"(b1));
}
__device__ __forceinline__ uint32_t f2u(float x) { return __float_as_uint(x); }

// Stage [128 x 64] fp32 (row stride ld) into hi/lo tf32 tiles, dst ld 68.
__device__ __forceinline__ void stage64(float* hi, float* lo,
                                        const float* __restrict__ src,
                                        int ld, int tid)
{
    for (int i4 = tid; i4 < 128 * 16; i4 += 256) {
        int r = i4 >> 4, k = (i4 & 15) * 4;
        float4 v = *(const float4*)&src[(size_t)r * ld + k];
        uint32_t hx = to_tf32(v.x), hy = to_tf32(v.y),
                 hz = to_tf32(v.z), hw = to_tf32(v.w);
        int o = r * 68 + k;
        *(uint4*)&hi[o] = make_uint4(hx, hy, hz, hw);
        *(uint4*)&lo[o] = make_uint4(to_tf32(v.x - __uint_as_float(hx)),
                                     to_tf32(v.y - __uint_as_float(hy)),
                                     to_tf32(v.z - __uint_as_float(hz)),
                                     to_tf32(v.w - __uint_as_float(hw)));
    }
}
// Stage [128 x 32] fp32 (row stride ld) into hi/lo tf32 tiles, dst ld 36.
__device__ __forceinline__ void stage32(float* hi, float* lo,
                                        const float* __restrict__ src,
                                        int ld, int tid)
{
    for (int i4 = tid; i4 < 128 * 8; i4 += 256) {
        int r = i4 >> 3, k = (i4 & 7) * 4;
        float4 v = *(const float4*)&src[(size_t)r * ld + k];
        uint32_t hx = to_tf32(v.x), hy = to_tf32(v.y),
                 hz = to_tf32(v.z), hw = to_tf32(v.w);
        int o = r * 36 + k;
        *(uint4*)&hi[o] = make_uint4(hx, hy, hz, hw);
        *(uint4*)&lo[o] = make_uint4(to_tf32(v.x - __uint_as_float(hx)),
                                     to_tf32(v.y - __uint_as_float(hy)),
                                     to_tf32(v.z - __uint_as_float(hz)),
                                     to_tf32(v.w - __uint_as_float(hw)));
    }
}

// One K=32 block-tile of split mma (3-pass). A tiles at (aH,aL) ld lda,
// B tiles at (bH,bL) ld ldb. Accum d[2][8][4], warp tile (wm, wn).
__device__ __forceinline__ void mma_k32(const float* aH, const float* aL, int lda,
                                        const float* bH, const float* bL, int ldb,
                                        float d[2][8][4],
                                        int wm, int wn, int qr, int qc)
{
    #pragma unroll 1
    for (int ks = 0; ks < 4; ks++) {
        const int kb = ks * 8 + qc;
        uint32_t ah[2][4], al[2][4];
        #pragma unroll
        for (int i = 0; i < 2; i++) {
            int r0 = (wm + i * 16 + qr) * lda;
            ah[i][0] = f2u(aH[r0 + kb]);
            ah[i][1] = f2u(aH[r0 + 8 * lda + kb]);
            ah[i][2] = f2u(aH[r0 + kb + 4]);
            ah[i][3] = f2u(aH[r0 + 8 * lda + kb + 4]);
            al[i][0] = f2u(aL[r0 + kb]);
            al[i][1] = f2u(aL[r0 + 8 * lda + kb]);
            al[i][2] = f2u(aL[r0 + kb + 4]);
            al[i][3] = f2u(aL[r0 + 8 * lda + kb + 4]);
        }
        #pragma unroll
        for (int j = 0; j < 8; j++) {
            int nb = (wn + j * 8 + qr) * ldb;
            uint32_t bh0 = f2u(bH[nb + kb]);
            uint32_t bh1 = f2u(bH[nb + kb + 4]);
            uint32_t bl0 = f2u(bL[nb + kb]);
            uint32_t bl1 = f2u(bL[nb + kb + 4]);
            #pragma unroll
            for (int i = 0; i < 2; i++) {
                mma_tf32(d[i][j], ah[i], bh0, bh1);
                mma_tf32(d[i][j], ah[i], bl0, bl1);
                mma_tf32(d[i][j], al[i], bh0, bh1);
            }
        }
    }
}

// ================= KV GEMM (swapped, persistent, 2 CTAs/SM) =================
// SMEM: AH [128][68] @0, AL @8704, BH [128][36] @17408, BL @22016. 26624 fl.
#define KV_SMEM (26624 * 4)   // 106496 B

__global__ void __launch_bounds__(256, 2)
kv_gemm(const float* __restrict__ lanes, const float* __restrict__ Wk,
        const float* __restrict__ Wv)
{
    extern __shared__ float sm[];
    float* AH = sm;
    float* AL = sm + 8704;
    float* BH = sm + 17408;
    float* BL = sm + 22016;
    const int tid = threadIdx.x, wid = tid >> 5, lane = tid & 31;
    const int qr = lane >> 2, qc = lane & 3;
    const int nt = blockIdx.x / 296, b2 = blockIdx.x % 296;
    const int wm = (wid >> 1) * 32, wn = (wid & 1) * 64;

    stage64(AH, AL, nt ? Wv : Wk, 64, tid);
    float* dst = nt ? g_V : g_K;

    #pragma unroll 1
    for (int ntile = b2; ntile < 1024; ntile += 296) {
        float d[2][8][4];
        #pragma unroll
        for (int i = 0; i < 2; i++)
            #pragma unroll
            for (int j = 0; j < 8; j++)
                d[i][j][0] = d[i][j][1] = d[i][j][2] = d[i][j][3] = 0.f;

        #pragma unroll 1
        for (int ch = 0; ch < 2; ch++) {
            __syncthreads();
            stage32(BH, BL, lanes + (size_t)ntile * 128 * 64 + ch * 32, 64, tid);
            __syncthreads();
            mma_k32(AH + ch * 32, AL + ch * 32, 68, BH, BL, 36,
                    d, wm, wn, qr, qc);
        }

        const int u0 = ntile * 2;
        #pragma unroll
        for (int i = 0; i < 2; i++)
            #pragma unroll
            for (int j = 0; j < 8; j++) {
                int g = wm + i * 16 + qr;
                int c = wn + j * 8 + 2 * qc;
                int u = u0 + (c >> 6), l = c & 63;
                *(float2*)&dst[(size_t)u * 8192 + g * 64 + l] =
                    make_float2(d[i][j][0], d[i][j][1]);
                *(float2*)&dst[(size_t)u * 8192 + (g + 8) * 64 + l] =
                    make_float2(d[i][j][2], d[i][j][3]);
            }
    }
}

// ================= Q / Y GEMM (K=128 in 4 chunks, 2 CTAs/SM) =================
// SMEM: AH @0, AL @4608, BH @9216, BL @13824, each [128][36]. 18432 fl.
#define QY_SMEM (18432 * 4)   // 73728 B

__global__ void __launch_bounds__(256, 2)
q_gemm(const float* __restrict__ veh, const float* __restrict__ Wq)
{
    extern __shared__ float sm[];
    float* AH = sm;
    float* AL = sm + 4608;
    float* BH = sm + 9216;
    float* BL = sm + 13824;
    const int tid = threadIdx.x, wid = tid >> 5, lane = tid & 31;
    const int qr = lane >> 2, qc = lane & 3;
    const int m0 = blockIdx.x * 128;
    const int wm = (wid >> 1) * 32, wn = (wid & 1) * 64;

    float d[2][8][4];
    #pragma unroll
    for (int i = 0; i < 2; i++)
        #pragma unroll
        for (int j = 0; j < 8; j++)
            d[i][j][0] = d[i][j][1] = d[i][j][2] = d[i][j][3] = 0.f;

    #pragma unroll 1
    for (int ch = 0; ch < 4; ch++) {
        stage32(AH, AL, veh + (size_t)m0 * 128 + ch * 32, 128, tid);
        stage32(BH, BL, Wq + ch * 32, 128, tid);
        __syncthreads();
        mma_k32(AH, AL, 36, BH, BL, 36, d, wm, wn, qr, qc);
        __syncthreads();
    }

    #pragma unroll
    for (int i = 0; i < 2; i++)
        #pragma unroll
        for (int j = 0; j < 8; j++) {
            int r = m0 + wm + i * 16 + qr, c = wn + j * 8 + 2 * qc;
            *(float2*)&g_Q[(size_t)r * 128 + c]       = make_float2(d[i][j][0], d[i][j][1]);
            *(float2*)&g_Q[(size_t)(r + 8) * 128 + c] = make_float2(d[i][j][2], d[i][j][3]);
        }
}

__global__ void __launch_bounds__(256, 2)
y_gemm(const float* __restrict__ Wc, const float* __restrict__ veh,
       float* __restrict__ out)
{
    extern __shared__ float sm[];
    float* AH = sm;
    float* AL = sm + 4608;
    float* BH = sm + 9216;
    float* BL = sm + 13824;
    const int tid = threadIdx.x, wid = tid >> 5, lane = tid & 31;
    const int qr = lane >> 2, qc = lane & 3;
    const int m0 = blockIdx.x * 128;
    const int wm = (wid >> 1) * 32, wn = (wid & 1) * 64;

    float d[2][8][4];
    #pragma unroll
    for (int i = 0; i < 2; i++)
        #pragma unroll
        for (int j = 0; j < 8; j++)
            d[i][j][0] = d[i][j][1] = d[i][j][2] = d[i][j][3] = 0.f;

    #pragma unroll 1
    for (int ch = 0; ch < 4; ch++) {
        stage32(AH, AL, g_O + (size_t)m0 * 128 + ch * 32, 128, tid);
        stage32(BH, BL, Wc + ch * 32, 128, tid);
        __syncthreads();
        mma_k32(AH, AL, 36, BH, BL, 36, d, wm, wn, qr, qc);
        __syncthreads();
    }

    #pragma unroll
    for (int i = 0; i < 2; i++)
        #pragma unroll
        for (int j = 0; j < 8; j++) {
            int r = m0 + wm + i * 16 + qr, c = wn + j * 8 + 2 * qc;
            size_t o0 = (size_t)r * 128 + c, o1 = (size_t)(r + 8) * 128 + c;
            float2 x0 = *(const float2*)&veh[o0];
            float2 x1 = *(const float2*)&veh[o1];
            *(float2*)&out[o0] = make_float2(d[i][j][0] + x0.x, d[i][j][1] + x0.y);
            *(float2*)&out[o1] = make_float2(d[i][j][2] + x1.x, d[i][j][3] + x1.y);
        }
}

// ================= attention kernel (fp32, per-unit) =================
#define AKT_OFF 0
#define AVT_OFF 8320
#define AQ_OFF  16640
#define AP_OFF  20600
#define A_SMEM_FLOATS 28280   // 113120 B -> 2 CTAs/SM

__device__ __forceinline__ u64 ffma2(u64 a, u64 b, u64 c) {
    u64 d;
    asm("fma.rn.f32x2 %0, %1, %2, %3;" : "=l"(d) : "l"(a), "l"(b), "l"(c));
    return d;
}
__device__ __forceinline__ u64 dup2(float x) {
    u64 d; asm("mov.b64 %0, {%1, %1};" : "=l"(d) : "f"(x)); return d;
}
__device__ __forceinline__ u64 pack2(float lo, float hi) {
    u64 d; asm("mov.b64 %0, {%1, %2};" : "=l"(d) : "f"(lo), "f"(hi)); return d;
}
__device__ __forceinline__ float2 unpack2(u64 a) {
    float2 r; asm("mov.b64 {%0, %1}, %2;" : "=f"(r.x), "=f"(r.y) : "l"(a)); return r;
}

__global__ void __launch_bounds__(512, 2)
attn_kernel(const int* __restrict__ maskl)
{
    extern __shared__ float sm[];
    const int tid  = threadIdx.x;
    const int w    = tid >> 5;
    const int lane = tid & 31;
    const int bid  = blockIdx.x;
    const int ah   = w & 3;
    const int atw  = w >> 2;

    int mi0 = 0, mi1 = 0;
    #pragma unroll
    for (int th = 0; th < THN; th++) {
        const int* mp = maskl + (size_t)(th * NUNIT + bid) * LL;
        mi0 |= mp[lane];
        mi1 |= mp[lane + 32];
    }
    const bool km0 = (mi0 != 0), km1 = (mi1 != 0);

    {
        const float* kp = g_K + (size_t)bid * 8192;
        const float* vp = g_V + (size_t)bid * 8192;
        for (int idx = tid; idx < 8192; idx += 512) {
            int g = idx >> 6, l = idx & 63;
            sm[AKT_OFF + g * 65 + l] = kp[idx];
            sm[AVT_OFF + g * 65 + l] = vp[idx];
        }
        for (int idx = tid; idx < TT * FF; idx += 512) {
            int t = idx >> 7, g = idx & 127;
            sm[AQ_OFF + t * 132 + g] = g_Q[(size_t)(t * NUNIT + bid) * 128 + g];
        }
    }
    __syncthreads();

    {
        const int gb = ah * 32;
        u64 acc[8] = {0,0,0,0,0,0,0,0};
        #pragma unroll 2
        for (int d = 0; d < 32; d += 4) {
            u64 kk[4];
            #pragma unroll
            for (int j = 0; j < 4; j++) {
                float k0 = sm[AKT_OFF + (gb + d + j) * 65 + lane];
                float k1 = sm[AKT_OFF + (gb + d + j) * 65 + lane + 32];
                kk[j] = pack2(k0, k1);
            }
            #pragma unroll
            for (int it = 0; it < 8; it++) {
                int tr = atw * 8 + it; tr = tr < TT ? tr : (TT - 1);
                float4 q = *(const float4*)&sm[AQ_OFF + tr * 132 + gb + d];
                acc[it] = ffma2(dup2(q.x), kk[0], acc[it]);
                acc[it] = ffma2(dup2(q.y), kk[1], acc[it]);
                acc[it] = ffma2(dup2(q.z), kk[2], acc[it]);
                acc[it] = ffma2(dup2(q.w), kk[3], acc[it]);
            }
        }
        const float scale = 0.17677669529663687f;
        #pragma unroll
        for (int it = 0; it < 8; it++) {
            int t = atw * 8 + it;
            if (t >= TT) break;
            float2 sc = unpack2(acc[it]);
            float s0 = km0 ? sc.x * scale : -1e9f;
            float s1 = km1 ? sc.y * scale : -1e9f;
            float m = fmaxf(s0, s1);
            #pragma unroll
            for (int o = 16; o; o >>= 1) m = fmaxf(m, __shfl_xor_sync(0xffffffffu, m, o));
            float e0 = __expf(s0 - m), e1 = __expf(s1 - m);
            float ss = e0 + e1;
            #pragma unroll
            for (int o = 16; o; o >>= 1) ss += __shfl_xor_sync(0xffffffffu, ss, o);
            float inv = 1.0f / ss;
            sm[AP_OFF + t * 256 + ah * 64 + lane]      = e0 * inv;
            sm[AP_OFF + t * 256 + ah * 64 + lane + 32] = e1 * inv;
        }
    }
    __syncthreads();

    {
        const int gb = ah * 32;
        const int vrow = AVT_OFF + (gb + lane) * 65;
        float oacc[8] = {0,0,0,0,0,0,0,0};
        #pragma unroll 2
        for (int l = 0; l < LL; l += 4) {
            float v0 = sm[vrow + l + 0];
            float v1 = sm[vrow + l + 1];
            float v2 = sm[vrow + l + 2];
            float v3 = sm[vrow + l + 3];
            #pragma unroll
            for (int it = 0; it < 8; it++) {
                int tr = atw * 8 + it; tr = tr < TT ? tr : (TT - 1);
                float4 p = *(const float4*)&sm[AP_OFF + tr * 256 + ah * 64 + l];
                oacc[it] = fmaf(p.x, v0, fmaf(p.y, v1, fmaf(p.z, v2, fmaf(p.w, v3, oacc[it]))));
            }
        }
        #pragma unroll
        for (int it = 0; it < 8; it++) {
            int t = atw * 8 + it;
            if (t < TT)
                g_O[(size_t)(t * NUNIT + bid) * 128 + gb + lane] = oacc[it];
        }
    }
}

// ================= launcher =================
extern "C" void kernel_launch(void* const* d_in, const int* in_sizes, int n_in,
                              void* d_out, int out_size)
{
    const float* veh   = (const float*)d_in[0];
    const float* lanes = (const float*)d_in[1];
    const int*   maskl = (const int*)d_in[2];
    const float* Wk    = (const float*)d_in[3];
    const float* Wv    = (const float*)d_in[4];
    const float* Wq    = (const float*)d_in[5];
    const float* Wc    = (const float*)d_in[6];
    float* out = (float*)d_out;

    cudaFuncSetAttribute(kv_gemm, cudaFuncAttributeMaxDynamicSharedMemorySize, KV_SMEM);
    cudaFuncSetAttribute(q_gemm,  cudaFuncAttributeMaxDynamicSharedMemorySize, QY_SMEM);
    cudaFuncSetAttribute(y_gemm,  cudaFuncAttributeMaxDynamicSharedMemorySize, QY_SMEM);
    cudaFuncSetAttribute(attn_kernel, cudaFuncAttributeMaxDynamicSharedMemorySize,
                         A_SMEM_FLOATS * (int)sizeof(float));

    kv_gemm<<<2 * 296, 256, KV_SMEM>>>(lanes, Wk, Wv);
    q_gemm<<<NROWQ / 128, 256, QY_SMEM>>>(veh, Wq);
    attn_kernel<<<NUNIT, 512, A_SMEM_FLOATS * sizeof(float)>>>(maskl);
    y_gemm<<<NROWQ / 128, 256, QY_SMEM>>>(Wc, veh, out);
}

// round 12
// speedup vs baseline: 1.2471x; 1.0473x over previous
#include <cuda_runtime.h>
#include <cstdint>

// LaneAttention, sm_103: merged projection kernel (KV persistent + Q tiles,
// block-range dispatch) + fp32 attention + Y gemm. mma.sync tf32 3-pass split.

#define TT    30
#define FF    128
#define LL    64
#define LFN   64
#define THN   20
#define NUNIT 2048
#define NROWQ (TT*NUNIT)   // 61440

#define KV_BLOCKS (2 * 296)          // 592
#define Q_BLOCKS  (NROWQ / 128)      // 480
#define PROJ_BLOCKS (KV_BLOCKS + Q_BLOCKS)

typedef unsigned long long u64;

// ---------------- scratch ----------------
__device__ float g_K[NUNIT * 128 * 64];
__device__ float g_V[NUNIT * 128 * 64];
__device__ float g_Q[NROWQ * 128];
__device__ float g_O[NROWQ * 128];

// ---------------- tf32 helpers ----------------
__device__ __forceinline__ uint32_t to_tf32(float x) {
    uint32_t r;
    asm("cvt.rna.tf32.f32 %0, %1;" : "=r"(r) : "f"(x));
    return r;
}
__device__ __forceinline__ void mma_tf32(float* d, const uint32_t* a,
                                         uint32_t b0, uint32_t b1) {
    asm volatile(
        "mma.sync.aligned.m16n8k8.row.col.f32.tf32.tf32.f32 "
        "{%0,%1,%2,%3}, {%4,%5,%6,%7}, {%8,%9}, {%0,%1,%2,%3};"
        : "+f"(d[0]), "+f"(d[1]), "+f"(d[2]), "+f"(d[3])
        : "r"(a[0]), "r"(a[1]), "r"(a[2]), "r"(a[3]), "r"(b0), "r"(b1));
}
__device__ __forceinline__ uint32_t f2u(float x) { return __float_as_uint(x); }

// Stage [128 x 64] fp32 (row stride ld) into hi/lo tf32 tiles, dst ld 68.
__device__ __forceinline__ void stage64(float* hi, float* lo,
                                        const float* __restrict__ src,
                                        int ld, int tid)
{
    for (int i4 = tid; i4 < 128 * 16; i4 += 256) {
        int r = i4 >> 4, k = (i4 & 15) * 4;
        float4 v = *(const float4*)&src[(size_t)r * ld + k];
        uint32_t hx = to_tf32(v.x), hy = to_tf32(v.y),
                 hz = to_tf32(v.z), hw = to_tf32(v.w);
        int o = r * 68 + k;
        *(uint4*)&hi[o] = make_uint4(hx, hy, hz, hw);
        *(uint4*)&lo[o] = make_uint4(to_tf32(v.x - __uint_as_float(hx)),
                                     to_tf32(v.y - __uint_as_float(hy)),
                                     to_tf32(v.z - __uint_as_float(hz)),
                                     to_tf32(v.w - __uint_as_float(hw)));
    }
}
// Stage [128 x 32] fp32 (row stride ld) into hi/lo tf32 tiles, dst ld 36.
__device__ __forceinline__ void stage32(float* hi, float* lo,
                                        const float* __restrict__ src,
                                        int ld, int tid)
{
    for (int i4 = tid; i4 < 128 * 8; i4 += 256) {
        int r = i4 >> 3, k = (i4 & 7) * 4;
        float4 v = *(const float4*)&src[(size_t)r * ld + k];
        uint32_t hx = to_tf32(v.x), hy = to_tf32(v.y),
                 hz = to_tf32(v.z), hw = to_tf32(v.w);
        int o = r * 36 + k;
        *(uint4*)&hi[o] = make_uint4(hx, hy, hz, hw);
        *(uint4*)&lo[o] = make_uint4(to_tf32(v.x - __uint_as_float(hx)),
                                     to_tf32(v.y - __uint_as_float(hy)),
                                     to_tf32(v.z - __uint_as_float(hz)),
                                     to_tf32(v.w - __uint_as_float(hw)));
    }
}

// One K=32 block-tile of split mma (3-pass).
__device__ __forceinline__ void mma_k32(const float* aH, const float* aL, int lda,
                                        const float* bH, const float* bL, int ldb,
                                        float d[2][8][4],
                                        int wm, int wn, int qr, int qc)
{
    #pragma unroll 1
    for (int ks = 0; ks < 4; ks++) {
        const int kb = ks * 8 + qc;
        uint32_t ah[2][4], al[2][4];
        #pragma unroll
        for (int i = 0; i < 2; i++) {
            int r0 = (wm + i * 16 + qr) * lda;
            ah[i][0] = f2u(aH[r0 + kb]);
            ah[i][1] = f2u(aH[r0 + 8 * lda + kb]);
            ah[i][2] = f2u(aH[r0 + kb + 4]);
            ah[i][3] = f2u(aH[r0 + 8 * lda + kb + 4]);
            al[i][0] = f2u(aL[r0 + kb]);
            al[i][1] = f2u(aL[r0 + 8 * lda + kb]);
            al[i][2] = f2u(aL[r0 + kb + 4]);
            al[i][3] = f2u(aL[r0 + 8 * lda + kb + 4]);
        }
        #pragma unroll
        for (int j = 0; j < 8; j++) {
            int nb = (wn + j * 8 + qr) * ldb;
            uint32_t bh0 = f2u(bH[nb + kb]);
            uint32_t bh1 = f2u(bH[nb + kb + 4]);
            uint32_t bl0 = f2u(bL[nb + kb]);
            uint32_t bl1 = f2u(bL[nb + kb + 4]);
            #pragma unroll
            for (int i = 0; i < 2; i++) {
                mma_tf32(d[i][j], ah[i], bh0, bh1);
                mma_tf32(d[i][j], ah[i], bl0, bl1);
                mma_tf32(d[i][j], al[i], bh0, bh1);
            }
        }
    }
}

// ================= merged projection kernel =================
// blocks [0, 592): KV role (persistent swapped). SMEM: AH[128][68]@0, AL@8704,
//                  BH[128][36]@17408, BL@22016. (106496 B requested)
// blocks [592, 1072): Q role. SMEM: AH@0 ld36, AL@4608, BH@9216, BL@13824.
#define PROJ_SMEM (26624 * 4)   // 106496 B -> 2 CTAs/SM for both roles

__global__ void __launch_bounds__(256, 2)
proj_gemm(const float* __restrict__ lanes, const float* __restrict__ Wk,
          const float* __restrict__ Wv, const float* __restrict__ veh,
          const float* __restrict__ Wq)
{
    extern __shared__ float sm[];
    const int tid = threadIdx.x, wid = tid >> 5, lane = tid & 31;
    const int qr = lane >> 2, qc = lane & 3;
    const int wm = (wid >> 1) * 32, wn = (wid & 1) * 64;

    if (blockIdx.x < KV_BLOCKS) {
        // ---------------- KV role ----------------
        float* AH = sm;
        float* AL = sm + 8704;
        float* BH = sm + 17408;
        float* BL = sm + 22016;
        const int nt = blockIdx.x / 296, b2 = blockIdx.x % 296;

        stage64(AH, AL, nt ? Wv : Wk, 64, tid);
        float* dst = nt ? g_V : g_K;

        #pragma unroll 1
        for (int ntile = b2; ntile < 1024; ntile += 296) {
            float d[2][8][4];
            #pragma unroll
            for (int i = 0; i < 2; i++)
                #pragma unroll
                for (int j = 0; j < 8; j++)
                    d[i][j][0] = d[i][j][1] = d[i][j][2] = d[i][j][3] = 0.f;

            #pragma unroll 1
            for (int ch = 0; ch < 2; ch++) {
                __syncthreads();
                stage32(BH, BL, lanes + (size_t)ntile * 128 * 64 + ch * 32, 64, tid);
                __syncthreads();
                mma_k32(AH + ch * 32, AL + ch * 32, 68, BH, BL, 36,
                        d, wm, wn, qr, qc);
            }

            const int u0 = ntile * 2;
            #pragma unroll
            for (int i = 0; i < 2; i++)
                #pragma unroll
                for (int j = 0; j < 8; j++) {
                    int g = wm + i * 16 + qr;
                    int c = wn + j * 8 + 2 * qc;
                    int u = u0 + (c >> 6), l = c & 63;
                    *(float2*)&dst[(size_t)u * 8192 + g * 64 + l] =
                        make_float2(d[i][j][0], d[i][j][1]);
                    *(float2*)&dst[(size_t)u * 8192 + (g + 8) * 64 + l] =
                        make_float2(d[i][j][2], d[i][j][3]);
                }
        }
    } else {
        // ---------------- Q role ----------------
        float* AH = sm;
        float* AL = sm + 4608;
        float* BH = sm + 9216;
        float* BL = sm + 13824;
        const int m0 = (blockIdx.x - KV_BLOCKS) * 128;

        float d[2][8][4];
        #pragma unroll
        for (int i = 0; i < 2; i++)
            #pragma unroll
            for (int j = 0; j < 8; j++)
                d[i][j][0] = d[i][j][1] = d[i][j][2] = d[i][j][3] = 0.f;

        #pragma unroll 1
        for (int ch = 0; ch < 4; ch++) {
            stage32(AH, AL, veh + (size_t)m0 * 128 + ch * 32, 128, tid);
            stage32(BH, BL, Wq + ch * 32, 128, tid);
            __syncthreads();
            mma_k32(AH, AL, 36, BH, BL, 36, d, wm, wn, qr, qc);
            __syncthreads();
        }

        #pragma unroll
        for (int i = 0; i < 2; i++)
            #pragma unroll
            for (int j = 0; j < 8; j++) {
                int r = m0 + wm + i * 16 + qr, c = wn + j * 8 + 2 * qc;
                *(float2*)&g_Q[(size_t)r * 128 + c]       = make_float2(d[i][j][0], d[i][j][1]);
                *(float2*)&g_Q[(size_t)(r + 8) * 128 + c] = make_float2(d[i][j][2], d[i][j][3]);
            }
    }
}

// ================= Y GEMM (K=128 in 4 chunks, 2 CTAs/SM) =================
#define QY_SMEM (18432 * 4)   // 73728 B

__global__ void __launch_bounds__(256, 2)
y_gemm(const float* __restrict__ Wc, const float* __restrict__ veh,
       float* __restrict__ out)
{
    extern __shared__ float sm[];
    float* AH = sm;
    float* AL = sm + 4608;
    float* BH = sm + 9216;
    float* BL = sm + 13824;
    const int tid = threadIdx.x, wid = tid >> 5, lane = tid & 31;
    const int qr = lane >> 2, qc = lane & 3;
    const int m0 = blockIdx.x * 128;
    const int wm = (wid >> 1) * 32, wn = (wid & 1) * 64;

    float d[2][8][4];
    #pragma unroll
    for (int i = 0; i < 2; i++)
        #pragma unroll
        for (int j = 0; j < 8; j++)
            d[i][j][0] = d[i][j][1] = d[i][j][2] = d[i][j][3] = 0.f;

    #pragma unroll 1
    for (int ch = 0; ch < 4; ch++) {
        stage32(AH, AL, g_O + (size_t)m0 * 128 + ch * 32, 128, tid);
        stage32(BH, BL, Wc + ch * 32, 128, tid);
        __syncthreads();
        mma_k32(AH, AL, 36, BH, BL, 36, d, wm, wn, qr, qc);
        __syncthreads();
    }

    #pragma unroll
    for (int i = 0; i < 2; i++)
        #pragma unroll
        for (int j = 0; j < 8; j++) {
            int r = m0 + wm + i * 16 + qr, c = wn + j * 8 + 2 * qc;
            size_t o0 = (size_t)r * 128 + c, o1 = (size_t)(r + 8) * 128 + c;
            float2 x0 = *(const float2*)&veh[o0];
            float2 x1 = *(const float2*)&veh[o1];
            *(float2*)&out[o0] = make_float2(d[i][j][0] + x0.x, d[i][j][1] + x0.y);
            *(float2*)&out[o1] = make_float2(d[i][j][2] + x1.x, d[i][j][3] + x1.y);
        }
}

// ================= attention kernel (fp32, per-unit) =================
#define AKT_OFF 0
#define AVT_OFF 8320
#define AQ_OFF  16640
#define AP_OFF  20600
#define A_SMEM_FLOATS 28280   // 113120 B -> 2 CTAs/SM

__device__ __forceinline__ u64 ffma2(u64 a, u64 b, u64 c) {
    u64 d;
    asm("fma.rn.f32x2 %0, %1, %2, %3;" : "=l"(d) : "l"(a), "l"(b), "l"(c));
    return d;
}
__device__ __forceinline__ u64 dup2(float x) {
    u64 d; asm("mov.b64 %0, {%1, %1};" : "=l"(d) : "f"(x)); return d;
}
__device__ __forceinline__ u64 pack2(float lo, float hi) {
    u64 d; asm("mov.b64 %0, {%1, %2};" : "=l"(d) : "f"(lo), "f"(hi)); return d;
}
__device__ __forceinline__ float2 unpack2(u64 a) {
    float2 r; asm("mov.b64 {%0, %1}, %2;" : "=f"(r.x), "=f"(r.y) : "l"(a)); return r;
}

__global__ void __launch_bounds__(512, 2)
attn_kernel(const int* __restrict__ maskl)
{
    extern __shared__ float sm[];
    const int tid  = threadIdx.x;
    const int w    = tid >> 5;
    const int lane = tid & 31;
    const int bid  = blockIdx.x;
    const int ah   = w & 3;
    const int atw  = w >> 2;

    int mi0 = 0, mi1 = 0;
    #pragma unroll
    for (int th = 0; th < THN; th++) {
        const int* mp = maskl + (size_t)(th * NUNIT + bid) * LL;
        mi0 |= mp[lane];
        mi1 |= mp[lane + 32];
    }
    const bool km0 = (mi0 != 0), km1 = (mi1 != 0);

    {
        const float* kp = g_K + (size_t)bid * 8192;
        const float* vp = g_V + (size_t)bid * 8192;
        for (int idx = tid; idx < 8192; idx += 512) {
            int g = idx >> 6, l = idx & 63;
            sm[AKT_OFF + g * 65 + l] = kp[idx];
            sm[AVT_OFF + g * 65 + l] = vp[idx];
        }
        for (int idx = tid; idx < TT * FF; idx += 512) {
            int t = idx >> 7, g = idx & 127;
            sm[AQ_OFF + t * 132 + g] = g_Q[(size_t)(t * NUNIT + bid) * 128 + g];
        }
    }
    __syncthreads();

    {
        const int gb = ah * 32;
        u64 acc[8] = {0,0,0,0,0,0,0,0};
        #pragma unroll 2
        for (int d = 0; d < 32; d += 4) {
            u64 kk[4];
            #pragma unroll
            for (int j = 0; j < 4; j++) {
                float k0 = sm[AKT_OFF + (gb + d + j) * 65 + lane];
                float k1 = sm[AKT_OFF + (gb + d + j) * 65 + lane + 32];
                kk[j] = pack2(k0, k1);
            }
            #pragma unroll
            for (int it = 0; it < 8; it++) {
                int tr = atw * 8 + it; tr = tr < TT ? tr : (TT - 1);
                float4 q = *(const float4*)&sm[AQ_OFF + tr * 132 + gb + d];
                acc[it] = ffma2(dup2(q.x), kk[0], acc[it]);
                acc[it] = ffma2(dup2(q.y), kk[1], acc[it]);
                acc[it] = ffma2(dup2(q.z), kk[2], acc[it]);
                acc[it] = ffma2(dup2(q.w), kk[3], acc[it]);
            }
        }
        const float scale = 0.17677669529663687f;
        #pragma unroll
        for (int it = 0; it < 8; it++) {
            int t = atw * 8 + it;
            if (t >= TT) break;
            float2 sc = unpack2(acc[it]);
            float s0 = km0 ? sc.x * scale : -1e9f;
            float s1 = km1 ? sc.y * scale : -1e9f;
            float m = fmaxf(s0, s1);
            #pragma unroll
            for (int o = 16; o; o >>= 1) m = fmaxf(m, __shfl_xor_sync(0xffffffffu, m, o));
            float e0 = __expf(s0 - m), e1 = __expf(s1 - m);
            float ss = e0 + e1;
            #pragma unroll
            for (int o = 16; o; o >>= 1) ss += __shfl_xor_sync(0xffffffffu, ss, o);
            float inv = 1.0f / ss;
            sm[AP_OFF + t * 256 + ah * 64 + lane]      = e0 * inv;
            sm[AP_OFF + t * 256 + ah * 64 + lane + 32] = e1 * inv;
        }
    }
    __syncthreads();

    {
        const int gb = ah * 32;
        const int vrow = AVT_OFF + (gb + lane) * 65;
        float oacc[8] = {0,0,0,0,0,0,0,0};
        #pragma unroll 2
        for (int l = 0; l < LL; l += 4) {
            float v0 = sm[vrow + l + 0];
            float v1 = sm[vrow + l + 1];
            float v2 = sm[vrow + l + 2];
            float v3 = sm[vrow + l + 3];
            #pragma unroll
            for (int it = 0; it < 8; it++) {
                int tr = atw * 8 + it; tr = tr < TT ? tr : (TT - 1);
                float4 p = *(const float4*)&sm[AP_OFF + tr * 256 + ah * 64 + l];
                oacc[it] = fmaf(p.x, v0, fmaf(p.y, v1, fmaf(p.z, v2, fmaf(p.w, v3, oacc[it]))));
            }
        }
        #pragma unroll
        for (int it = 0; it < 8; it++) {
            int t = atw * 8 + it;
            if (t < TT)
                g_O[(size_t)(t * NUNIT + bid) * 128 + gb + lane] = oacc[it];
        }
    }
}

// ================= launcher =================
extern "C" void kernel_launch(void* const* d_in, const int* in_sizes, int n_in,
                              void* d_out, int out_size)
{
    const float* veh   = (const float*)d_in[0];
    const float* lanes = (const float*)d_in[1];
    const int*   maskl = (const int*)d_in[2];
    const float* Wk    = (const float*)d_in[3];
    const float* Wv    = (const float*)d_in[4];
    const float* Wq    = (const float*)d_in[5];
    const float* Wc    = (const float*)d_in[6];
    float* out = (float*)d_out;

    cudaFuncSetAttribute(proj_gemm, cudaFuncAttributeMaxDynamicSharedMemorySize, PROJ_SMEM);
    cudaFuncSetAttribute(y_gemm,   cudaFuncAttributeMaxDynamicSharedMemorySize, QY_SMEM);
    cudaFuncSetAttribute(attn_kernel, cudaFuncAttributeMaxDynamicSharedMemorySize,
                         A_SMEM_FLOATS * (int)sizeof(float));

    proj_gemm<<<PROJ_BLOCKS, 256, PROJ_SMEM>>>(lanes, Wk, Wv, veh, Wq);
    attn_kernel<<<NUNIT, 512, A_SMEM_FLOATS * sizeof(float)>>>(maskl);
    y_gemm<<<Q_BLOCKS, 256, QY_SMEM>>>(Wc, veh, out);
}

// round 13
// speedup vs baseline: 1.3426x; 1.0766x over previous
#include <cuda_runtime.h>
#include <cstdint>

// LaneAttention, sm_103: merged projection kernel (KV persistent + Q tiles)
// with register-prefetch software pipelining + fp32 attention + Y gemm.

#define TT    30
#define FF    128
#define LL    64
#define LFN   64
#define THN   20
#define NUNIT 2048
#define NROWQ (TT*NUNIT)   // 61440

#define KV_BLOCKS (2 * 296)          // 592
#define Q_BLOCKS  (NROWQ / 128)      // 480
#define PROJ_BLOCKS (KV_BLOCKS + Q_BLOCKS)

typedef unsigned long long u64;

// ---------------- scratch ----------------
__device__ float g_K[NUNIT * 128 * 64];
__device__ float g_V[NUNIT * 128 * 64];
__device__ float g_Q[NROWQ * 128];
__device__ float g_O[NROWQ * 128];

// ---------------- tf32 helpers ----------------
__device__ __forceinline__ uint32_t to_tf32(float x) {
    uint32_t r;
    asm("cvt.rna.tf32.f32 %0, %1;" : "=r"(r) : "f"(x));
    return r;
}
__device__ __forceinline__ void mma_tf32(float* d, const uint32_t* a,
                                         uint32_t b0, uint32_t b1) {
    asm volatile(
        "mma.sync.aligned.m16n8k8.row.col.f32.tf32.tf32.f32 "
        "{%0,%1,%2,%3}, {%4,%5,%6,%7}, {%8,%9}, {%0,%1,%2,%3};"
        : "+f"(d[0]), "+f"(d[1]), "+f"(d[2]), "+f"(d[3])
        : "r"(a[0]), "r"(a[1]), "r"(a[2]), "r"(a[3]), "r"(b0), "r"(b1));
}
__device__ __forceinline__ uint32_t f2u(float x) { return __float_as_uint(x); }

// Stage [128 x 64] fp32 (row stride ld) into hi/lo tf32 tiles, dst ld 68.
__device__ __forceinline__ void stage64(float* hi, float* lo,
                                        const float* __restrict__ src,
                                        int ld, int tid)
{
    for (int i4 = tid; i4 < 128 * 16; i4 += 256) {
        int r = i4 >> 4, k = (i4 & 15) * 4;
        float4 v = *(const float4*)&src[(size_t)r * ld + k];
        uint32_t hx = to_tf32(v.x), hy = to_tf32(v.y),
                 hz = to_tf32(v.z), hw = to_tf32(v.w);
        int o = r * 68 + k;
        *(uint4*)&hi[o] = make_uint4(hx, hy, hz, hw);
        *(uint4*)&lo[o] = make_uint4(to_tf32(v.x - __uint_as_float(hx)),
                                     to_tf32(v.y - __uint_as_float(hy)),
                                     to_tf32(v.z - __uint_as_float(hz)),
                                     to_tf32(v.w - __uint_as_float(hw)));
    }
}
// Stage [128 x 32] fp32 (row stride ld) into hi/lo tf32 tiles, dst ld 36.
__device__ __forceinline__ void stage32(float* hi, float* lo,
                                        const float* __restrict__ src,
                                        int ld, int tid)
{
    for (int i4 = tid; i4 < 128 * 8; i4 += 256) {
        int r = i4 >> 3, k = (i4 & 7) * 4;
        float4 v = *(const float4*)&src[(size_t)r * ld + k];
        uint32_t hx = to_tf32(v.x), hy = to_tf32(v.y),
                 hz = to_tf32(v.z), hw = to_tf32(v.w);
        int o = r * 36 + k;
        *(uint4*)&hi[o] = make_uint4(hx, hy, hz, hw);
        *(uint4*)&lo[o] = make_uint4(to_tf32(v.x - __uint_as_float(hx)),
                                     to_tf32(v.y - __uint_as_float(hy)),
                                     to_tf32(v.z - __uint_as_float(hz)),
                                     to_tf32(v.w - __uint_as_float(hw)));
    }
}
// Prefetch one [128 x 32] chunk into registers (4 float4 per thread).
__device__ __forceinline__ void prefetch32(float4 pf[4],
                                           const float* __restrict__ src,
                                           int ld, int tid)
{
    #pragma unroll
    for (int j = 0; j < 4; j++) {
        int i4 = tid + j * 256;
        int r = i4 >> 3, k = (i4 & 7) * 4;
        pf[j] = *(const float4*)&src[(size_t)r * ld + k];
    }
}
// Convert + store prefetched chunk into hi/lo tf32 tiles, dst ld 36.
__device__ __forceinline__ void commit32(float* hi, float* lo,
                                         const float4 pf[4], int tid)
{
    #pragma unroll
    for (int j = 0; j < 4; j++) {
        int i4 = tid + j * 256;
        int r = i4 >> 3, k = (i4 & 7) * 4;
        float4 v = pf[j];
        uint32_t hx = to_tf32(v.x), hy = to_tf32(v.y),
                 hz = to_tf32(v.z), hw = to_tf32(v.w);
        int o = r * 36 + k;
        *(uint4*)&hi[o] = make_uint4(hx, hy, hz, hw);
        *(uint4*)&lo[o] = make_uint4(to_tf32(v.x - __uint_as_float(hx)),
                                     to_tf32(v.y - __uint_as_float(hy)),
                                     to_tf32(v.z - __uint_as_float(hz)),
                                     to_tf32(v.w - __uint_as_float(hw)));
    }
}

// One K=32 block-tile of split mma (3-pass).
__device__ __forceinline__ void mma_k32(const float* aH, const float* aL, int lda,
                                        const float* bH, const float* bL, int ldb,
                                        float d[2][8][4],
                                        int wm, int wn, int qr, int qc)
{
    #pragma unroll 1
    for (int ks = 0; ks < 4; ks++) {
        const int kb = ks * 8 + qc;
        uint32_t ah[2][4], al[2][4];
        #pragma unroll
        for (int i = 0; i < 2; i++) {
            int r0 = (wm + i * 16 + qr) * lda;
            ah[i][0] = f2u(aH[r0 + kb]);
            ah[i][1] = f2u(aH[r0 + 8 * lda + kb]);
            ah[i][2] = f2u(aH[r0 + kb + 4]);
            ah[i][3] = f2u(aH[r0 + 8 * lda + kb + 4]);
            al[i][0] = f2u(aL[r0 + kb]);
            al[i][1] = f2u(aL[r0 + 8 * lda + kb]);
            al[i][2] = f2u(aL[r0 + kb + 4]);
            al[i][3] = f2u(aL[r0 + 8 * lda + kb + 4]);
        }
        #pragma unroll
        for (int j = 0; j < 8; j++) {
            int nb = (wn + j * 8 + qr) * ldb;
            uint32_t bh0 = f2u(bH[nb + kb]);
            uint32_t bh1 = f2u(bH[nb + kb + 4]);
            uint32_t bl0 = f2u(bL[nb + kb]);
            uint32_t bl1 = f2u(bL[nb + kb + 4]);
            #pragma unroll
            for (int i = 0; i < 2; i++) {
                mma_tf32(d[i][j], ah[i], bh0, bh1);
                mma_tf32(d[i][j], ah[i], bl0, bl1);
                mma_tf32(d[i][j], al[i], bh0, bh1);
            }
        }
    }
}

// ================= merged projection kernel =================
#define PROJ_SMEM (26624 * 4)   // 106496 B -> 2 CTAs/SM for both roles

__global__ void __launch_bounds__(256, 2)
proj_gemm(const float* __restrict__ lanes, const float* __restrict__ Wk,
          const float* __restrict__ Wv, const float* __restrict__ veh,
          const float* __restrict__ Wq)
{
    extern __shared__ float sm[];
    const int tid = threadIdx.x, wid = tid >> 5, lane = tid & 31;
    const int qr = lane >> 2, qc = lane & 3;
    const int wm = (wid >> 1) * 32, wn = (wid & 1) * 64;

    if (blockIdx.x < KV_BLOCKS) {
        // ---------------- KV role (persistent, pipelined B) ----------------
        float* AH = sm;
        float* AL = sm + 8704;
        float* BH = sm + 17408;
        float* BL = sm + 22016;
        const int nt = blockIdx.x / 296, b2 = blockIdx.x % 296;

        stage64(AH, AL, nt ? Wv : Wk, 64, tid);
        float* dst = nt ? g_V : g_K;

        float4 pf[4];
        prefetch32(pf, lanes + (size_t)b2 * 8192, 64, tid);

        #pragma unroll 1
        for (int ntile = b2; ntile < 1024; ntile += 296) {
            float d[2][8][4];
            #pragma unroll
            for (int i = 0; i < 2; i++)
                #pragma unroll
                for (int j = 0; j < 8; j++)
                    d[i][j][0] = d[i][j][1] = d[i][j][2] = d[i][j][3] = 0.f;

            #pragma unroll 1
            for (int ch = 0; ch < 2; ch++) {
                __syncthreads();            // prior mma done reading B
                commit32(BH, BL, pf, tid);
                __syncthreads();
                // prefetch next chunk (ch1 of this tile, or ch0 of next tile)
                if (ch == 0) {
                    prefetch32(pf, lanes + (size_t)ntile * 8192 + 32, 64, tid);
                } else if (ntile + 296 < 1024) {
                    prefetch32(pf, lanes + (size_t)(ntile + 296) * 8192, 64, tid);
                }
                mma_k32(AH + ch * 32, AL + ch * 32, 68, BH, BL, 36,
                        d, wm, wn, qr, qc);
            }

            const int u0 = ntile * 2;
            #pragma unroll
            for (int i = 0; i < 2; i++)
                #pragma unroll
                for (int j = 0; j < 8; j++) {
                    int g = wm + i * 16 + qr;
                    int c = wn + j * 8 + 2 * qc;
                    int u = u0 + (c >> 6), l = c & 63;
                    *(float2*)&dst[(size_t)u * 8192 + g * 64 + l] =
                        make_float2(d[i][j][0], d[i][j][1]);
                    *(float2*)&dst[(size_t)u * 8192 + (g + 8) * 64 + l] =
                        make_float2(d[i][j][2], d[i][j][3]);
                }
        }
    } else {
        // ---------------- Q role (pipelined A) ----------------
        float* AH = sm;
        float* AL = sm + 4608;
        float* BH = sm + 9216;
        float* BL = sm + 13824;
        const int m0 = (blockIdx.x - KV_BLOCKS) * 128;

        float d[2][8][4];
        #pragma unroll
        for (int i = 0; i < 2; i++)
            #pragma unroll
            for (int j = 0; j < 8; j++)
                d[i][j][0] = d[i][j][1] = d[i][j][2] = d[i][j][3] = 0.f;

        float4 pf[4];
        prefetch32(pf, veh + (size_t)m0 * 128, 128, tid);

        #pragma unroll 1
        for (int ch = 0; ch < 4; ch++) {
            commit32(AH, AL, pf, tid);
            stage32(BH, BL, Wq + ch * 32, 128, tid);
            __syncthreads();
            if (ch < 3)
                prefetch32(pf, veh + (size_t)m0 * 128 + (ch + 1) * 32, 128, tid);
            mma_k32(AH, AL, 36, BH, BL, 36, d, wm, wn, qr, qc);
            __syncthreads();
        }

        #pragma unroll
        for (int i = 0; i < 2; i++)
            #pragma unroll
            for (int j = 0; j < 8; j++) {
                int r = m0 + wm + i * 16 + qr, c = wn + j * 8 + 2 * qc;
                *(float2*)&g_Q[(size_t)r * 128 + c]       = make_float2(d[i][j][0], d[i][j][1]);
                *(float2*)&g_Q[(size_t)(r + 8) * 128 + c] = make_float2(d[i][j][2], d[i][j][3]);
            }
    }
}

// ================= Y GEMM (pipelined A) =================
#define QY_SMEM (18432 * 4)   // 73728 B

__global__ void __launch_bounds__(256, 2)
y_gemm(const float* __restrict__ Wc, const float* __restrict__ veh,
       float* __restrict__ out)
{
    extern __shared__ float sm[];
    float* AH = sm;
    float* AL = sm + 4608;
    float* BH = sm + 9216;
    float* BL = sm + 13824;
    const int tid = threadIdx.x, wid = tid >> 5, lane = tid & 31;
    const int qr = lane >> 2, qc = lane & 3;
    const int m0 = blockIdx.x * 128;
    const int wm = (wid >> 1) * 32, wn = (wid & 1) * 64;

    float d[2][8][4];
    #pragma unroll
    for (int i = 0; i < 2; i++)
        #pragma unroll
        for (int j = 0; j < 8; j++)
            d[i][j][0] = d[i][j][1] = d[i][j][2] = d[i][j][3] = 0.f;

    float4 pf[4];
    prefetch32(pf, g_O + (size_t)m0 * 128, 128, tid);

    #pragma unroll 1
    for (int ch = 0; ch < 4; ch++) {
        commit32(AH, AL, pf, tid);
        stage32(BH, BL, Wc + ch * 32, 128, tid);
        __syncthreads();
        if (ch < 3)
            prefetch32(pf, g_O + (size_t)m0 * 128 + (ch + 1) * 32, 128, tid);
        mma_k32(AH, AL, 36, BH, BL, 36, d, wm, wn, qr, qc);
        __syncthreads();
    }

    #pragma unroll
    for (int i = 0; i < 2; i++)
        #pragma unroll
        for (int j = 0; j < 8; j++) {
            int r = m0 + wm + i * 16 + qr, c = wn + j * 8 + 2 * qc;
            size_t o0 = (size_t)r * 128 + c, o1 = (size_t)(r + 8) * 128 + c;
            float2 x0 = *(const float2*)&veh[o0];
            float2 x1 = *(const float2*)&veh[o1];
            *(float2*)&out[o0] = make_float2(d[i][j][0] + x0.x, d[i][j][1] + x0.y);
            *(float2*)&out[o1] = make_float2(d[i][j][2] + x1.x, d[i][j][3] + x1.y);
        }
}

// ================= attention kernel (fp32, per-unit) =================
#define AKT_OFF 0
#define AVT_OFF 8320
#define AQ_OFF  16640
#define AP_OFF  20600
#define A_SMEM_FLOATS 28280   // 113120 B -> 2 CTAs/SM

__device__ __forceinline__ u64 ffma2(u64 a, u64 b, u64 c) {
    u64 d;
    asm("fma.rn.f32x2 %0, %1, %2, %3;" : "=l"(d) : "l"(a), "l"(b), "l"(c));
    return d;
}
__device__ __forceinline__ u64 dup2(float x) {
    u64 d; asm("mov.b64 %0, {%1, %1};" : "=l"(d) : "f"(x)); return d;
}
__device__ __forceinline__ u64 pack2(float lo, float hi) {
    u64 d; asm("mov.b64 %0, {%1, %2};" : "=l"(d) : "f"(lo), "f"(hi)); return d;
}
__device__ __forceinline__ float2 unpack2(u64 a) {
    float2 r; asm("mov.b64 {%0, %1}, %2;" : "=f"(r.x), "=f"(r.y) : "l"(a)); return r;
}

__global__ void __launch_bounds__(512, 2)
attn_kernel(const int* __restrict__ maskl)
{
    extern __shared__ float sm[];
    const int tid  = threadIdx.x;
    const int w    = tid >> 5;
    const int lane = tid & 31;
    const int bid  = blockIdx.x;
    const int ah   = w & 3;
    const int atw  = w >> 2;

    int mi0 = 0, mi1 = 0;
    #pragma unroll
    for (int th = 0; th < THN; th++) {
        const int* mp = maskl + (size_t)(th * NUNIT + bid) * LL;
        mi0 |= mp[lane];
        mi1 |= mp[lane + 32];
    }
    const bool km0 = (mi0 != 0), km1 = (mi1 != 0);

    {
        const float* kp = g_K + (size_t)bid * 8192;
        const float* vp = g_V + (size_t)bid * 8192;
        for (int idx = tid; idx < 8192; idx += 512) {
            int g = idx >> 6, l = idx & 63;
            sm[AKT_OFF + g * 65 + l] = kp[idx];
            sm[AVT_OFF + g * 65 + l] = vp[idx];
        }
        for (int idx = tid; idx < TT * FF; idx += 512) {
            int t = idx >> 7, g = idx & 127;
            sm[AQ_OFF + t * 132 + g] = g_Q[(size_t)(t * NUNIT + bid) * 128 + g];
        }
    }
    __syncthreads();

    {
        const int gb = ah * 32;
        u64 acc[8] = {0,0,0,0,0,0,0,0};
        #pragma unroll 2
        for (int d = 0; d < 32; d += 4) {
            u64 kk[4];
            #pragma unroll
            for (int j = 0; j < 4; j++) {
                float k0 = sm[AKT_OFF + (gb + d + j) * 65 + lane];
                float k1 = sm[AKT_OFF + (gb + d + j) * 65 + lane + 32];
                kk[j] = pack2(k0, k1);
            }
            #pragma unroll
            for (int it = 0; it < 8; it++) {
                int tr = atw * 8 + it; tr = tr < TT ? tr : (TT - 1);
                float4 q = *(const float4*)&sm[AQ_OFF + tr * 132 + gb + d];
                acc[it] = ffma2(dup2(q.x), kk[0], acc[it]);
                acc[it] = ffma2(dup2(q.y), kk[1], acc[it]);
                acc[it] = ffma2(dup2(q.z), kk[2], acc[it]);
                acc[it] = ffma2(dup2(q.w), kk[3], acc[it]);
            }
        }
        const float scale = 0.17677669529663687f;
        #pragma unroll
        for (int it = 0; it < 8; it++) {
            int t = atw * 8 + it;
            if (t >= TT) break;
            float2 sc = unpack2(acc[it]);
            float s0 = km0 ? sc.x * scale : -1e9f;
            float s1 = km1 ? sc.y * scale : -1e9f;
            float m = fmaxf(s0, s1);
            #pragma unroll
            for (int o = 16; o; o >>= 1) m = fmaxf(m, __shfl_xor_sync(0xffffffffu, m, o));
            float e0 = __expf(s0 - m), e1 = __expf(s1 - m);
            float ss = e0 + e1;
            #pragma unroll
            for (int o = 16; o; o >>= 1) ss += __shfl_xor_sync(0xffffffffu, ss, o);
            float inv = 1.0f / ss;
            sm[AP_OFF + t * 256 + ah * 64 + lane]      = e0 * inv;
            sm[AP_OFF + t * 256 + ah * 64 + lane + 32] = e1 * inv;
        }
    }
    __syncthreads();

    {
        const int gb = ah * 32;
        const int vrow = AVT_OFF + (gb + lane) * 65;
        float oacc[8] = {0,0,0,0,0,0,0,0};
        #pragma unroll 2
        for (int l = 0; l < LL; l += 4) {
            float v0 = sm[vrow + l + 0];
            float v1 = sm[vrow + l + 1];
            float v2 = sm[vrow + l + 2];
            float v3 = sm[vrow + l + 3];
            #pragma unroll
            for (int it = 0; it < 8; it++) {
                int tr = atw * 8 + it; tr = tr < TT ? tr : (TT - 1);
                float4 p = *(const float4*)&sm[AP_OFF + tr * 256 + ah * 64 + l];
                oacc[it] = fmaf(p.x, v0, fmaf(p.y, v1, fmaf(p.z, v2, fmaf(p.w, v3, oacc[it]))));
            }
        }
        #pragma unroll
        for (int it = 0; it < 8; it++) {
            int t = atw * 8 + it;
            if (t < TT)
                g_O[(size_t)(t * NUNIT + bid) * 128 + gb + lane] = oacc[it];
        }
    }
}

// ================= launcher =================
extern "C" void kernel_launch(void* const* d_in, const int* in_sizes, int n_in,
                              void* d_out, int out_size)
{
    const float* veh   = (const float*)d_in[0];
    const float* lanes = (const float*)d_in[1];
    const int*   maskl = (const int*)d_in[2];
    const float* Wk    = (const float*)d_in[3];
    const float* Wv    = (const float*)d_in[4];
    const float* Wq    = (const float*)d_in[5];
    const float* Wc    = (const float*)d_in[6];
    float* out = (float*)d_out;

    cudaFuncSetAttribute(proj_gemm, cudaFuncAttributeMaxDynamicSharedMemorySize, PROJ_SMEM);
    cudaFuncSetAttribute(y_gemm,   cudaFuncAttributeMaxDynamicSharedMemorySize, QY_SMEM);
    cudaFuncSetAttribute(attn_kernel, cudaFuncAttributeMaxDynamicSharedMemorySize,
                         A_SMEM_FLOATS * (int)sizeof(float));

    proj_gemm<<<PROJ_BLOCKS, 256, PROJ_SMEM>>>(lanes, Wk, Wv, veh, Wq);
    attn_kernel<<<NUNIT, 512, A_SMEM_FLOATS * sizeof(float)>>>(maskl);
    y_gemm<<<Q_BLOCKS, 256, QY_SMEM>>>(Wc, veh, out);
}